// round 4
// baseline (speedup 1.0000x reference)
#include <cuda_runtime.h>

#define BB 64
#define TT 512
#define II 512
#define HH 1024
#define NCTA_DIR 64   // CTAs per direction; 128 total <= 148 SMs -> all co-resident

// ---------------- scratch (device globals; no allocations allowed) ----------
__device__ float g_Xrz[2][TT][BB][2 * HH]; // x@W_xr|x@W_xz (+bias), combined cols
__device__ float g_Xh [2][TT][BB][HH];     // x@W_xh (+bias)
__device__ float g_h  [2][BB][HH];         // current hidden state per direction
__device__ float g_RH [2][BB][HH];         // R * h   (phase1 -> phase2)
__device__ float g_Z  [2][BB][HH];         // Z gate  (phase1 -> phase2)
__device__ unsigned g_bar_count[2];
__device__ unsigned g_bar_gen[2];

// ---------------- packed f32x2 helpers (Blackwell) --------------------------
__device__ __forceinline__ void fma2(unsigned long long& d,
                                     unsigned long long a, unsigned long long b) {
    asm("fma.rn.f32x2 %0, %1, %2, %0;" : "+l"(d) : "l"(a), "l"(b));
}
__device__ __forceinline__ unsigned long long pack2(float lo, float hi) {
    unsigned long long r;
    asm("mov.b64 %0, {%1, %2};" : "=l"(r) : "f"(lo), "f"(hi));
    return r;
}
__device__ __forceinline__ float sum2(unsigned long long v) {
    float lo, hi;
    asm("mov.b64 {%0, %1}, %2;" : "=f"(lo), "=f"(hi) : "l"(v));
    return lo + hi;
}

// ------------- per-direction software grid barrier (generation-based) -------
__device__ __forceinline__ void dir_barrier(int dir) {
    __syncthreads();
    if (threadIdx.x == 0) {
        volatile unsigned* vgen = (volatile unsigned*)&g_bar_gen[dir];
        unsigned my = *vgen;
        __threadfence();
        unsigned a = atomicAdd(&g_bar_count[dir], 1u);
        if (a == NCTA_DIR - 1) {
            g_bar_count[dir] = 0;
            __threadfence();
            atomicAdd(&g_bar_gen[dir], 1u);
        } else {
            while (*vgen == my) { }
            __threadfence();
        }
    }
    __syncthreads();
}

// ---------------- input projection: 6x GEMM (32768x512)@(512x1024)+bias -----
// CTA: 256 threads -> 64x64 tile, thread = 4 rows x 4 cols, f32x2 k-pairs
__global__ void __launch_bounds__(256) inproj_kernel(
    const float* __restrict__ x,
    const float* __restrict__ Wr_f, const float* __restrict__ br_f,
    const float* __restrict__ Wz_f, const float* __restrict__ bz_f,
    const float* __restrict__ Wh_f, const float* __restrict__ bh_f,
    const float* __restrict__ Wr_b, const float* __restrict__ br_b,
    const float* __restrict__ Wz_b, const float* __restrict__ bz_b,
    const float* __restrict__ Wh_b, const float* __restrict__ bh_b)
{
    const int mat  = blockIdx.z;   // 0..5 : dir*3 + gate
    const int dir  = mat / 3;
    const int gate = mat % 3;      // 0=r, 1=z, 2=h
    const float* W; const float* bias;
    switch (mat) {
        case 0: W = Wr_f; bias = br_f; break;
        case 1: W = Wz_f; bias = bz_f; break;
        case 2: W = Wh_f; bias = bh_f; break;
        case 3: W = Wr_b; bias = br_b; break;
        case 4: W = Wz_b; bias = bz_b; break;
        default: W = Wh_b; bias = bh_b; break;
    }

    const int mTile = blockIdx.x;                 // 512 row tiles of 64
    const int cTile = blockIdx.y;                 // 16 col tiles of 64
    const int rg    = (threadIdx.x >> 4) * 4;     // 4 rows per thread
    const int jc    = cTile * 64 + (threadIdx.x & 15) * 4;  // 4 cols per thread

    __shared__ float xs[64][68];
    unsigned long long acc2[4][4];
    #pragma unroll
    for (int r = 0; r < 4; ++r)
        #pragma unroll
        for (int cc = 0; cc < 4; ++cc) acc2[r][cc] = 0ull;

    const float* xbase = x + (size_t)(mTile * 64) * II;

    #pragma unroll 1
    for (int kb = 0; kb < II; kb += 64) {
        #pragma unroll
        for (int u = 0; u < 4; ++u) {
            int e  = threadIdx.x + 256 * u;   // 0..1023
            int r  = e >> 4;
            int c4 = (e & 15) * 4;
            *(float4*)&xs[r][c4] = *(const float4*)(xbase + r * II + kb + c4);
        }
        __syncthreads();
        #pragma unroll
        for (int k4 = 0; k4 < 16; ++k4) {
            const int k = kb + 4 * k4;
            const float4 w0 = *(const float4*)&W[(k + 0) * HH + jc];
            const float4 w1 = *(const float4*)&W[(k + 1) * HH + jc];
            const float4 w2 = *(const float4*)&W[(k + 2) * HH + jc];
            const float4 w3 = *(const float4*)&W[(k + 3) * HH + jc];
            unsigned long long wp0[4], wp1[4];
            wp0[0] = pack2(w0.x, w1.x); wp1[0] = pack2(w2.x, w3.x);
            wp0[1] = pack2(w0.y, w1.y); wp1[1] = pack2(w2.y, w3.y);
            wp0[2] = pack2(w0.z, w1.z); wp1[2] = pack2(w2.z, w3.z);
            wp0[3] = pack2(w0.w, w1.w); wp1[3] = pack2(w2.w, w3.w);
            #pragma unroll
            for (int r = 0; r < 4; ++r) {
                ulonglong2 xu = *(const ulonglong2*)&xs[rg + r][4 * k4];
                #pragma unroll
                for (int cc = 0; cc < 4; ++cc) {
                    fma2(acc2[r][cc], xu.x, wp0[cc]);
                    fma2(acc2[r][cc], xu.y, wp1[cc]);
                }
            }
        }
        __syncthreads();
    }

    const float4 bv = *(const float4*)&bias[jc];
    #pragma unroll
    for (int r = 0; r < 4; ++r) {
        int row = mTile * 64 + rg + r;   // row = b*T + t
        int b   = row >> 9;
        int t   = row & (TT - 1);
        float4 v;
        v.x = sum2(acc2[r][0]) + bv.x;
        v.y = sum2(acc2[r][1]) + bv.y;
        v.z = sum2(acc2[r][2]) + bv.z;
        v.w = sum2(acc2[r][3]) + bv.w;
        if (gate == 0)      *(float4*)&g_Xrz[dir][t][b][jc]      = v;
        else if (gate == 1) *(float4*)&g_Xrz[dir][t][b][HH + jc] = v;
        else                *(float4*)&g_Xh [dir][t][b][jc]      = v;
    }
}

// ---------------- persistent bidirectional GRU recurrence -------------------
// 128 CTAs x 512 threads, 1 CTA/SM. Recurrent weights SMEM-resident; staged
// h/RH tiles double-buffered; all FMAs are packed f32x2 over k-pairs.
// Dynamic smem (floats):
//   Wrz4 [32768] : phase1 weights  [(k>>2)*128 + col*4 + (k&3)], col=0..31
//   Wh24 [16384] : phase2 weights  [(k>>2)*64  + col*4 + (k&3)], col=0..15
//   ts [2][64][68] : double-buffered staging tile (68-float row pitch)
#define SM_WH2 32768
#define SM_TS  49152
#define SM_FLOATS (49152 + 2 * 64 * 68)

__global__ void __launch_bounds__(512) gru_rec_kernel(
    const float* __restrict__ hf0, const float* __restrict__ hb0,
    const float* __restrict__ Whr_f, const float* __restrict__ Whz_f, const float* __restrict__ Whh_f,
    const float* __restrict__ Whr_b, const float* __restrict__ Whz_b, const float* __restrict__ Whh_b,
    float* __restrict__ out)
{
    extern __shared__ float sm[];
    float* Wrz4 = sm;
    float* Wh24 = sm + SM_WH2;
    float (*ts)[64][68] = (float(*)[64][68])(sm + SM_TS);

    const int tid  = threadIdx.x;
    const int dir  = blockIdx.x >> 6;
    const int c    = blockIdx.x & 63;
    const int w    = tid >> 5;
    const int lane = tid & 31;

    const float* __restrict__ Whr = dir ? Whr_b : Whr_f;
    const float* __restrict__ Whz = dir ? Whz_b : Whz_f;
    const float* __restrict__ Whh = dir ? Whh_b : Whh_f;
    const float* __restrict__ h0  = dir ? hb0   : hf0;

    float* __restrict__ hstate = &g_h [dir][0][0];
    float* __restrict__ RH     = &g_RH[dir][0][0];
    float* __restrict__ Zb     = &g_Z [dir][0][0];

    const bool isR = (c < 32);                 // uniform per CTA
    const float* __restrict__ Wg = isR ? Whr : Whz;

    // ---- one-time: cache weight columns into SMEM ----
    {
        const int col = tid & 31;
        const int jwl = (c * 32 + col) & (HH - 1);
        for (int k = tid >> 5; k < HH; k += 16)
            Wrz4[(k >> 2) * 128 + col * 4 + (k & 3)] = Wg[k * HH + jwl];
        const int col2 = tid & 15;
        const int j2l  = c * 16 + col2;
        for (int k = tid >> 4; k < HH; k += 32)
            Wh24[(k >> 2) * 64 + col2 * 4 + (k & 3)] = Whh[k * HH + j2l];
    }
    // init hidden state (re-done every replay: deterministic)
    {
        int base = c * 1024;
        hstate[base + tid]       = h0[base + tid];
        hstate[base + 512 + tid] = h0[base + 512 + tid];
    }
    dir_barrier(dir);

    // phase1 geometry: 4 rows x 2 cols per thread (16 warps x 4 rows = 64)
    const int rb1 = w * 4;
    const int cp1 = lane & 15;
    const int j0  = c * 32 + cp1;
    const int j1  = j0 + 16;
    const int jw0 = j0 & (HH - 1);
    const int jw1 = j1 & (HH - 1);

    // phase2 geometry: 2 rows x 1 col per thread
    const int cp2 = lane & 15;
    const int rb2 = w * 4 + (lane >> 4) * 2;
    const int j2  = c * 16 + cp2;

    // staging geometry: 2 float4 per thread per 64-wide k-block
    int srow0, scol0, srow1, scol1;
    { int e = tid;       srow0 = e >> 4; scol0 = (e & 15) * 4; }
    { int e = tid + 512; srow1 = e >> 4; scol1 = (e & 15) * 4; }

    for (int step = 0; step < TT; ++step) {
        const int t = dir ? (TT - 1 - step) : step;

        // ---------------- phase 1: [R|Z] = sigmoid(h@W + x) ----------------
        const float* __restrict__ xrz = &g_Xrz[dir][t][0][0];
        float xp0[4], xp1[4], ho0[4] = {0,0,0,0}, ho1[4] = {0,0,0,0};
        #pragma unroll
        for (int r = 0; r < 4; ++r) {
            const int b = rb1 + r;
            xp0[r] = __ldg(&xrz[b * (2 * HH) + j0]);
            xp1[r] = __ldg(&xrz[b * (2 * HH) + j1]);
            if (isR) {
                ho0[r] = hstate[b * HH + jw0];
                ho1[r] = hstate[b * HH + jw1];
            }
        }

        *(float4*)&ts[0][srow0][scol0] = *(const float4*)&hstate[srow0 * HH + scol0];
        *(float4*)&ts[0][srow1][scol1] = *(const float4*)&hstate[srow1 * HH + scol1];
        __syncthreads();

        unsigned long long a0[4] = {0,0,0,0}, a1[4] = {0,0,0,0};
        #pragma unroll 1
        for (int i = 0; i < 16; ++i) {
            float4 pf0, pf1;
            if (i < 15) {
                const int kn = (i + 1) * 64;
                pf0 = *(const float4*)&hstate[srow0 * HH + kn + scol0];
                pf1 = *(const float4*)&hstate[srow1 * HH + kn + scol1];
            }
            const float (*tb)[68] = ts[i & 1];
            #pragma unroll
            for (int k4 = 0; k4 < 16; ++k4) {
                const int q = i * 16 + k4;
                ulonglong2 w0 = *(const ulonglong2*)&Wrz4[q * 128 + cp1 * 4];
                ulonglong2 w1 = *(const ulonglong2*)&Wrz4[q * 128 + (cp1 + 16) * 4];
                #pragma unroll
                for (int r = 0; r < 4; ++r) {
                    ulonglong2 hv = *(const ulonglong2*)&tb[rb1 + r][k4 * 4];
                    fma2(a0[r], hv.x, w0.x);
                    fma2(a0[r], hv.y, w0.y);
                    fma2(a1[r], hv.x, w1.x);
                    fma2(a1[r], hv.y, w1.y);
                }
            }
            if (i < 15) {
                *(float4*)&ts[(i + 1) & 1][srow0][scol0] = pf0;
                *(float4*)&ts[(i + 1) & 1][srow1][scol1] = pf1;
                __syncthreads();
            }
        }
        #pragma unroll
        for (int r = 0; r < 4; ++r) {
            const int b = rb1 + r;
            float s0 = 1.f / (1.f + __expf(-(sum2(a0[r]) + xp0[r])));
            float s1 = 1.f / (1.f + __expf(-(sum2(a1[r]) + xp1[r])));
            if (isR) {
                RH[b * HH + jw0] = s0 * ho0[r];
                RH[b * HH + jw1] = s1 * ho1[r];
            } else {
                Zb[b * HH + jw0] = s0;
                Zb[b * HH + jw1] = s1;
            }
        }
        dir_barrier(dir);

        // ---------------- phase 2: h = Z*tanh(RH@Whh + xh) + (1-Z)*h -------
        const float* __restrict__ xh = &g_Xh[dir][t][0][0];
        float xp2[2], zz[2], hh2[2];
        #pragma unroll
        for (int r = 0; r < 2; ++r) {
            const int b = rb2 + r;
            xp2[r] = __ldg(&xh[b * HH + j2]);
            zz[r]  = Zb[b * HH + j2];
            hh2[r] = hstate[b * HH + j2];
        }

        *(float4*)&ts[0][srow0][scol0] = *(const float4*)&RH[srow0 * HH + scol0];
        *(float4*)&ts[0][srow1][scol1] = *(const float4*)&RH[srow1 * HH + scol1];
        __syncthreads();

        unsigned long long a2[2] = {0, 0};
        #pragma unroll 1
        for (int i = 0; i < 16; ++i) {
            float4 pf0, pf1;
            if (i < 15) {
                const int kn = (i + 1) * 64;
                pf0 = *(const float4*)&RH[srow0 * HH + kn + scol0];
                pf1 = *(const float4*)&RH[srow1 * HH + kn + scol1];
            }
            const float (*tb)[68] = ts[i & 1];
            #pragma unroll
            for (int k4 = 0; k4 < 16; ++k4) {
                const int q = i * 16 + k4;
                ulonglong2 wv  = *(const ulonglong2*)&Wh24[q * 64 + cp2 * 4];
                ulonglong2 h0v = *(const ulonglong2*)&tb[rb2 + 0][k4 * 4];
                ulonglong2 h1v = *(const ulonglong2*)&tb[rb2 + 1][k4 * 4];
                fma2(a2[0], h0v.x, wv.x);
                fma2(a2[0], h0v.y, wv.y);
                fma2(a2[1], h1v.x, wv.x);
                fma2(a2[1], h1v.y, wv.y);
            }
            if (i < 15) {
                *(float4*)&ts[(i + 1) & 1][srow0][scol0] = pf0;
                *(float4*)&ts[(i + 1) & 1][srow1][scol1] = pf1;
                __syncthreads();
            }
        }
        #pragma unroll
        for (int r = 0; r < 2; ++r) {
            const int b = rb2 + r;
            float htil = tanhf(sum2(a2[r]) + xp2[r]);
            float hnew = zz[r] * htil + (1.f - zz[r]) * hh2[r];
            hstate[b * HH + j2] = hnew;
            out[(size_t)(b * TT + t) * (2 * HH) + dir * HH + j2] = hnew;
        }
        dir_barrier(dir);
    }
}

// ---------------------------------------------------------------------------
extern "C" void kernel_launch(void* const* d_in, const int* in_sizes, int n_in,
                              void* d_out, int out_size) {
    (void)in_sizes; (void)n_in; (void)out_size;
    const float* x     = (const float*)d_in[0];
    const float* hf0   = (const float*)d_in[1];
    const float* hb0   = (const float*)d_in[2];
    const float* Whr_f = (const float*)d_in[3];
    const float* Wxr_f = (const float*)d_in[4];
    const float* br_f  = (const float*)d_in[5];
    const float* Whz_f = (const float*)d_in[6];
    const float* Wxz_f = (const float*)d_in[7];
    const float* bz_f  = (const float*)d_in[8];
    const float* Whh_f = (const float*)d_in[9];
    const float* Wxh_f = (const float*)d_in[10];
    const float* bh_f  = (const float*)d_in[11];
    const float* Whr_b = (const float*)d_in[12];
    const float* Wxr_b = (const float*)d_in[13];
    const float* br_b  = (const float*)d_in[14];
    const float* Whz_b = (const float*)d_in[15];
    const float* Wxz_b = (const float*)d_in[16];
    const float* bz_b  = (const float*)d_in[17];
    const float* Whh_b = (const float*)d_in[18];
    const float* Wxh_b = (const float*)d_in[19];
    const float* bh_b  = (const float*)d_in[20];
    float* out = (float*)d_out;

    static int smem_set = 0;
    if (!smem_set) {
        cudaFuncSetAttribute(gru_rec_kernel,
                             cudaFuncAttributeMaxDynamicSharedMemorySize,
                             SM_FLOATS * sizeof(float));
        smem_set = 1;
    }

    dim3 g1(TT * BB / 64, HH / 64, 6);
    inproj_kernel<<<g1, 256>>>(x,
        Wxr_f, br_f, Wxz_f, bz_f, Wxh_f, bh_f,
        Wxr_b, br_b, Wxz_b, bz_b, Wxh_b, bh_b);

    gru_rec_kernel<<<2 * NCTA_DIR, 512, SM_FLOATS * sizeof(float)>>>(hf0, hb0,
        Whr_f, Whz_f, Whh_f, Whr_b, Whz_b, Whh_b, out);
}